// round 2
// baseline (speedup 1.0000x reference)
#include <cuda_runtime.h>

#define Dd 48
#define Hh 256
#define Ww 256
#define DMk 48
#define HMk 128
#define WMk 128
#define PHn 4
#define HALFW (Ww / 2)                 // 128 == blockDim.x of warp kernel
#define CS (Dd * Hh * Ww * 2)          // 6,291,456 floats per phase slab
#define MVF_CH (DMk * HMk * WMk)       // 786,432 floats per mvf channel

// ---------------------------------------------------------------------------
// Passthrough: out[:, 0] = image  (float4 vectorized copy)
// ---------------------------------------------------------------------------
__global__ void copy_image_kernel(const float4* __restrict__ src,
                                  float4* __restrict__ dst) {
    int i = blockIdx.x * blockDim.x + threadIdx.x;
    if (i < CS / 4) dst[i] = src[i];
}

// ---------------------------------------------------------------------------
// Trilinear grid-sample (zeros padding, absolute voxel coords) of the
// 2-channel channel-last image. Validity folded into per-axis weights;
// indices clamped so dead loads stay in bounds.
// ---------------------------------------------------------------------------
__device__ __forceinline__ float2 sample3d(const float2* __restrict__ img,
                                           float cz, float cy, float cx) {
    float zf = floorf(cz), yf = floorf(cy), xf = floorf(cx);
    float fz = cz - zf, fy = cy - yf, fx = cx - xf;
    int z0 = (int)zf, y0 = (int)yf, x0 = (int)xf;
    int z1 = z0 + 1, y1 = y0 + 1, x1 = x0 + 1;

    float wz[2], wy[2], wx[2];
    wz[0] = (1.f - fz) * (((unsigned)z0 < (unsigned)Dd) ? 1.f : 0.f);
    wz[1] = fz         * (((unsigned)z1 < (unsigned)Dd) ? 1.f : 0.f);
    wy[0] = (1.f - fy) * (((unsigned)y0 < (unsigned)Hh) ? 1.f : 0.f);
    wy[1] = fy         * (((unsigned)y1 < (unsigned)Hh) ? 1.f : 0.f);
    wx[0] = (1.f - fx) * (((unsigned)x0 < (unsigned)Ww) ? 1.f : 0.f);
    wx[1] = fx         * (((unsigned)x1 < (unsigned)Ww) ? 1.f : 0.f);

    int zi[2] = {min(max(z0, 0), Dd - 1), min(max(z1, 0), Dd - 1)};
    int yi[2] = {min(max(y0, 0), Hh - 1), min(max(y1, 0), Hh - 1)};
    int xi[2] = {min(max(x0, 0), Ww - 1), min(max(x1, 0), Ww - 1)};

    float ax = 0.f, ay = 0.f;
#pragma unroll
    for (int a = 0; a < 2; a++) {
#pragma unroll
        for (int b = 0; b < 2; b++) {
            float wzy = wz[a] * wy[b];
            int rb = (zi[a] * Hh + yi[b]) * Ww;
#pragma unroll
            for (int c = 0; c < 2; c++) {
                float w = wzy * wx[c];
                float2 v = __ldg(img + rb + xi[c]);
                ax = fmaf(w, v.x, ax);
                ay = fmaf(w, v.y, ay);
            }
        }
    }
    return make_float2(ax, ay);
}

// ---------------------------------------------------------------------------
// Fused: on-the-fly 2x linear upsample of mvf (H,W dims; D is identity;
// jax.image half-pixel convention, edge-clamp == JAX renormalization),
// flow scale (1,2,2), grid-sample, channel-last float4 store.
//
// Launch geometry: blockDim.x = 128 (= HALFW = WMk), grid = (Hh, Dd, PHn).
// threadIdx.x = tx handles output x-pair (2*tx, 2*tx+1); the three mvf
// row loads per channel are fully coalesced 128-wide rows.
// ---------------------------------------------------------------------------
__global__ void __launch_bounds__(128)
warp_kernel(const float* __restrict__ image,
            const float* __restrict__ mvf,
            float* __restrict__ out) {
    int tx = threadIdx.x;      // 0..127
    int y  = blockIdx.x;       // 0..255
    int z  = blockIdx.y;       // 0..47
    int ph = blockIdx.z;       // 0..3

    // y-dim resize taps: out[2k]=.25*in[k-1]+.75*in[k]; out[2k+1]=.75*in[k]+.25*in[k+1]
    int  yk   = y >> 1;
    bool yodd = (y & 1) != 0;
    int  ya   = yodd ? yk : (yk > 0 ? yk - 1 : 0);
    int  yb   = yodd ? (yk < HMk - 1 ? yk + 1 : HMk - 1) : yk;
    float wa  = yodd ? 0.75f : 0.25f;
    float wb  = 1.f - wa;

    // x taps shared by the even/odd output pair
    int xlo = (tx > 0) ? tx - 1 : 0;
    int xhi = (tx < WMk - 1) ? tx + 1 : WMk - 1;

    const float* mbase = mvf + (size_t)ph * 3 * MVF_CH + (size_t)z * HMk * WMk;

    float v_even[3], v_odd[3];
#pragma unroll
    for (int c = 0; c < 3; c++) {
        const float* rowa = mbase + (size_t)c * MVF_CH + ya * WMk;
        const float* rowb = mbase + (size_t)c * MVF_CH + yb * WMk;
        float lo  = fmaf(wa, __ldg(rowa + xlo), wb * __ldg(rowb + xlo));
        float mid = fmaf(wa, __ldg(rowa + tx),  wb * __ldg(rowb + tx));
        float hi  = fmaf(wa, __ldg(rowa + xhi), wb * __ldg(rowb + xhi));
        v_even[c] = fmaf(0.25f, lo,  0.75f * mid);
        v_odd[c]  = fmaf(0.75f, mid, 0.25f * hi);
    }

    int x0 = 2 * tx;
    const float2* img2 = (const float2*)image;

    // flow scale (1, 2, 2); coords are absolute voxel coordinates
    float2 r0 = sample3d(img2, (float)z + v_even[0],
                               (float)y + 2.f * v_even[1],
                               (float)x0 + 2.f * v_even[2]);
    float2 r1 = sample3d(img2, (float)z + v_odd[0],
                               (float)y + 2.f * v_odd[1],
                               (float)(x0 + 1) + 2.f * v_odd[2]);

    float4* o4 = (float4*)(out + (size_t)(1 + ph) * CS);
    o4[(z * Hh + y) * HALFW + tx] = make_float4(r0.x, r0.y, r1.x, r1.y);
}

// ---------------------------------------------------------------------------
extern "C" void kernel_launch(void* const* d_in, const int* in_sizes, int n_in,
                              void* d_out, int out_size) {
    const float* image = (const float*)d_in[0];   // (1,1,48,256,256,2) f32
    const float* mvf   = (const float*)d_in[1];   // (1,4,3,48,128,128) f32
    float* out = (float*)d_out;                   // (1,5,48,256,256,2) f32

    copy_image_kernel<<<(CS / 4 + 255) / 256, 256>>>((const float4*)image,
                                                     (float4*)out);

    dim3 grid(Hh, Dd, PHn);
    warp_kernel<<<grid, 128>>>(image, mvf, out);
}